// round 1
// baseline (speedup 1.0000x reference)
#include <cuda_runtime.h>
#include <math.h>

// ---------------------------------------------------------------------------
// Problem constants
// ---------------------------------------------------------------------------
constexpr int BB   = 2;
constexpr int SS   = 2048;
constexpr int EE   = 768;
constexpr int HH   = 12;
constexpr int DH   = 64;
constexpr int NN   = BB * SS;        // 4096 rows
constexpr int F3   = 3 * EE;         // 2304
constexpr int DD1  = 1536;
constexpr int KSP  = 8;              // spline basis count

// ---------------------------------------------------------------------------
// Static scratch (allocation-free rule: __device__ globals)
// ---------------------------------------------------------------------------
__device__ float g_qkv [NN * F3];          // 37.7 MB
__device__ float g_ao  [NN * EE];
__device__ float g_proj[NN * EE];
__device__ float g_h   [NN * EE];
__device__ float g_k0  [NN * DD1];
__device__ float g_k1  [NN * EE];
__device__ float g_b0  [NN * EE  * KSP];   // 100 MB
__device__ float g_b1  [NN * DD1 * KSP];   // 201 MB

// ---------------------------------------------------------------------------
// Helpers
// ---------------------------------------------------------------------------
__device__ __forceinline__ float siluf(float x) {
    return x / (1.0f + __expf(-x));
}

// Uniform grid knots: grid[i] = (i-3)*0.4 - 1, i = 0..11 (fp32, matches ref)
__device__ __forceinline__ float knot(int i) {
    return (float)(i - 3) * 0.4f - 1.0f;
}

// Cox–de Boor, SPLINE_ORDER=3, 8 output bases. Fully unrolled -> constants fold.
__device__ __forceinline__ void bspline8(float v, float* __restrict__ b) {
    float t[11];
#pragma unroll
    for (int i = 0; i < 11; i++)
        t[i] = (v >= knot(i) && v < knot(i + 1)) ? 1.0f : 0.0f;
#pragma unroll
    for (int k = 1; k <= 3; k++) {
#pragma unroll
        for (int i = 0; i < 11; i++) {
            if (i < 11 - k) {
                float dl = knot(i + k)     - knot(i);
                float dr = knot(i + k + 1) - knot(i + 1);
                t[i] = (v - knot(i)) * (1.0f / dl) * t[i]
                     + (knot(i + k + 1) - v) * (1.0f / dr) * t[i + 1];
            }
        }
    }
#pragma unroll
    for (int i = 0; i < 8; i++) b[i] = t[i];
}

// ---------------------------------------------------------------------------
// Generic NT GEMM:  C[n,m] (+)= sum_k A[n,k]*B[m,k]  (+ bias[m])
// A: N x K row-major, B: M x K row-major, C: N x M row-major
// ---------------------------------------------------------------------------
template<int BM, int BN, int BK, int TM, int TN, bool SILU_A, bool ACC, bool BIAS>
__global__ void __launch_bounds__(256)
gemm_nt(const float* __restrict__ A, const float* __restrict__ B,
        const float* __restrict__ bias, float* __restrict__ C,
        int N, int M, int K)
{
    __shared__ float As[BK][BM + 4];
    __shared__ float Bs[BK][BN + 4];

    const int tid = threadIdx.x;
    constexpr int NTX = BN / TN;           // threads along cols
    const int tx = tid % NTX;
    const int ty = tid / NTX;

    const int row0 = blockIdx.y * BM;
    const int col0 = blockIdx.x * BN;

    const float* Ab = A + (size_t)row0 * K;
    const float* Bb = B + (size_t)col0 * K;

    float acc[TM][TN];
#pragma unroll
    for (int i = 0; i < TM; i++)
#pragma unroll
        for (int j = 0; j < TN; j++) acc[i][j] = 0.0f;

    for (int k0 = 0; k0 < K; k0 += BK) {
        // ---- load A tile (BM x BK) as float4, store transposed ----
#pragma unroll
        for (int idx = tid; idx < (BM * BK) / 4; idx += 256) {
            int r  = idx / (BK / 4);
            int c4 = idx % (BK / 4);
            float4 v = *(const float4*)(Ab + (size_t)r * K + k0 + c4 * 4);
            if (SILU_A) {
                v.x = siluf(v.x); v.y = siluf(v.y);
                v.z = siluf(v.z); v.w = siluf(v.w);
            }
            As[c4 * 4 + 0][r] = v.x;
            As[c4 * 4 + 1][r] = v.y;
            As[c4 * 4 + 2][r] = v.z;
            As[c4 * 4 + 3][r] = v.w;
        }
        // ---- load B tile (BN x BK) ----
#pragma unroll
        for (int idx = tid; idx < (BN * BK) / 4; idx += 256) {
            int r  = idx / (BK / 4);
            int c4 = idx % (BK / 4);
            float4 v = *(const float4*)(Bb + (size_t)r * K + k0 + c4 * 4);
            Bs[c4 * 4 + 0][r] = v.x;
            Bs[c4 * 4 + 1][r] = v.y;
            Bs[c4 * 4 + 2][r] = v.z;
            Bs[c4 * 4 + 3][r] = v.w;
        }
        __syncthreads();

#pragma unroll
        for (int kk = 0; kk < BK; kk++) {
            float af[TM], bf[TN];
#pragma unroll
            for (int i4 = 0; i4 < TM / 4; i4++) {
                float4 v = *(const float4*)&As[kk][ty * TM + i4 * 4];
                af[i4 * 4 + 0] = v.x; af[i4 * 4 + 1] = v.y;
                af[i4 * 4 + 2] = v.z; af[i4 * 4 + 3] = v.w;
            }
#pragma unroll
            for (int j4 = 0; j4 < TN / 4; j4++) {
                float4 v = *(const float4*)&Bs[kk][tx * TN + j4 * 4];
                bf[j4 * 4 + 0] = v.x; bf[j4 * 4 + 1] = v.y;
                bf[j4 * 4 + 2] = v.z; bf[j4 * 4 + 3] = v.w;
            }
#pragma unroll
            for (int i = 0; i < TM; i++)
#pragma unroll
                for (int j = 0; j < TN; j++)
                    acc[i][j] = fmaf(af[i], bf[j], acc[i][j]);
        }
        __syncthreads();
    }

    // ---- epilogue ----
#pragma unroll
    for (int i = 0; i < TM; i++) {
        size_t base = (size_t)(row0 + ty * TM + i) * M + col0 + tx * TN;
#pragma unroll
        for (int j4 = 0; j4 < TN / 4; j4++) {
            float4 v = make_float4(acc[i][j4 * 4 + 0], acc[i][j4 * 4 + 1],
                                   acc[i][j4 * 4 + 2], acc[i][j4 * 4 + 3]);
            if (BIAS) {
                float4 bv = *(const float4*)(bias + col0 + tx * TN + j4 * 4);
                v.x += bv.x; v.y += bv.y; v.z += bv.z; v.w += bv.w;
            }
            if (ACC) {
                float4 c = *(const float4*)(C + base + j4 * 4);
                v.x += c.x; v.y += c.y; v.z += c.z; v.w += c.w;
            }
            *(float4*)(C + base + j4 * 4) = v;
        }
    }
}

// ---------------------------------------------------------------------------
// Flash attention, fp32. Bq=64 q-rows per block, stream k/v in tiles of 32.
// grid = (S/64, B*H), 256 threads.
// Thread map: quad = tid&7 owns 4 score cols; rg = tid>>3 owns rows {rg, rg+32}
// ---------------------------------------------------------------------------
__global__ void __launch_bounds__(256)
attn_kernel(const float* __restrict__ qkv, float* __restrict__ ao)
{
    constexpr int BQ = 64, BKT = 32;
    __shared__ float Qt[BQ][DH + 1];
    __shared__ float Kt[BKT][DH + 1];
    __shared__ float Vt[BKT][DH + 1];
    __shared__ float Pt[BQ][BKT + 4];

    const int bh = blockIdx.y;
    const int b  = bh / HH;
    const int h  = bh % HH;
    const int q0 = blockIdx.x * BQ;
    const int tid  = threadIdx.x;
    const int quad = tid & 7;
    const int rg   = tid >> 3;

    // load Q tile: 64 x 64
    {
        const float* qbase = qkv + ((size_t)(b * SS + q0)) * F3 + h * DH;
#pragma unroll
        for (int idx = tid; idx < BQ * (DH / 4); idx += 256) {
            int r  = idx >> 4;
            int c4 = idx & 15;
            float4 v = *(const float4*)(qbase + (size_t)r * F3 + c4 * 4);
            Qt[r][c4 * 4 + 0] = v.x; Qt[r][c4 * 4 + 1] = v.y;
            Qt[r][c4 * 4 + 2] = v.z; Qt[r][c4 * 4 + 3] = v.w;
        }
    }
    __syncthreads();

    float m[2] = {-1e30f, -1e30f};
    float l[2] = {0.0f, 0.0f};
    float acc_o[2][8];
#pragma unroll
    for (int jr = 0; jr < 2; jr++)
#pragma unroll
        for (int t = 0; t < 8; t++) acc_o[jr][t] = 0.0f;

    for (int kt = 0; kt < SS / BKT; kt++) {
        // load K and V tiles (32 x 64 each)
        const float* kb = qkv + ((size_t)(b * SS + kt * BKT)) * F3 + EE + h * DH;
        const float* vb = kb + EE;
#pragma unroll
        for (int idx = tid; idx < BKT * (DH / 4); idx += 256) {
            int r  = idx >> 4;
            int c4 = idx & 15;
            float4 kv = *(const float4*)(kb + (size_t)r * F3 + c4 * 4);
            Kt[r][c4 * 4 + 0] = kv.x; Kt[r][c4 * 4 + 1] = kv.y;
            Kt[r][c4 * 4 + 2] = kv.z; Kt[r][c4 * 4 + 3] = kv.w;
            float4 vv = *(const float4*)(vb + (size_t)r * F3 + c4 * 4);
            Vt[r][c4 * 4 + 0] = vv.x; Vt[r][c4 * 4 + 1] = vv.y;
            Vt[r][c4 * 4 + 2] = vv.z; Vt[r][c4 * 4 + 3] = vv.w;
        }
        __syncthreads();

        // S = Q K^T for my 2 rows x 4 cols
        float s[2][4] = {{0, 0, 0, 0}, {0, 0, 0, 0}};
#pragma unroll 4
        for (int d = 0; d < DH; d++) {
            float q0v = Qt[rg][d];
            float q1v = Qt[rg + 32][d];
#pragma unroll
            for (int jc = 0; jc < 4; jc++) {
                float kv = Kt[quad * 4 + jc][d];
                s[0][jc] = fmaf(q0v, kv, s[0][jc]);
                s[1][jc] = fmaf(q1v, kv, s[1][jc]);
            }
        }

        // online softmax per row (row = 8 lanes: quad 0..7)
#pragma unroll
        for (int jr = 0; jr < 2; jr++) {
            float sv[4];
            float mx = -1e30f;
#pragma unroll
            for (int jc = 0; jc < 4; jc++) {
                sv[jc] = s[jr][jc] * 0.125f;
                mx = fmaxf(mx, sv[jc]);
            }
#pragma unroll
            for (int o = 1; o < 8; o <<= 1)
                mx = fmaxf(mx, __shfl_xor_sync(0xffffffffu, mx, o));
            float newm = fmaxf(m[jr], mx);
            float lsum = 0.0f;
#pragma unroll
            for (int jc = 0; jc < 4; jc++) {
                float p = __expf(sv[jc] - newm);
                Pt[rg + jr * 32][quad * 4 + jc] = p;
                lsum += p;
            }
#pragma unroll
            for (int o = 1; o < 8; o <<= 1)
                lsum += __shfl_xor_sync(0xffffffffu, lsum, o);
            float corr = __expf(m[jr] - newm);
            l[jr] = l[jr] * corr + lsum;
            m[jr] = newm;
#pragma unroll
            for (int t = 0; t < 8; t++) acc_o[jr][t] *= corr;
        }
        __syncthreads();

        // O += P V
#pragma unroll 4
        for (int c = 0; c < BKT; c++) {
            float p0 = Pt[rg][c];
            float p1 = Pt[rg + 32][c];
#pragma unroll
            for (int t = 0; t < 8; t++) {
                float vv = Vt[c][quad + 8 * t];
                acc_o[0][t] = fmaf(p0, vv, acc_o[0][t]);
                acc_o[1][t] = fmaf(p1, vv, acc_o[1][t]);
            }
        }
        __syncthreads();
    }

    // write: ao[b, s, h*64 + dcol]
#pragma unroll
    for (int jr = 0; jr < 2; jr++) {
        float inv = 1.0f / l[jr];
        int srow = q0 + rg + jr * 32;
        float* op = ao + ((size_t)(b * SS + srow)) * EE + h * DH;
#pragma unroll
        for (int t = 0; t < 8; t++)
            op[quad + 8 * t] = acc_o[jr][t] * inv;
    }
}

// ---------------------------------------------------------------------------
// Fused residual + LayerNorm (+ optional sigmoid(terrain) gate).
// One block per row (768 cols, 256 threads x 3 elems).
// ---------------------------------------------------------------------------
template<bool GATE>
__global__ void __launch_bounds__(256)
ln_kernel(const float* __restrict__ a, const float* __restrict__ bsrc,
          const float* __restrict__ scale, const float* __restrict__ bias,
          const float* __restrict__ terrain, float* __restrict__ out)
{
    const int n = blockIdx.x;
    const int tid = threadIdx.x;
    const float* pa = a    + (size_t)n * EE;
    const float* pb = bsrc + (size_t)n * EE;

    float y[3];
    float s = 0.0f, ss = 0.0f;
#pragma unroll
    for (int t = 0; t < 3; t++) {
        int e = tid + t * 256;
        y[t] = pa[e] + pb[e];
        s  += y[t];
        ss += y[t] * y[t];
    }
#pragma unroll
    for (int o = 16; o > 0; o >>= 1) {
        s  += __shfl_down_sync(0xffffffffu, s,  o);
        ss += __shfl_down_sync(0xffffffffu, ss, o);
    }
    __shared__ float red[2][8];
    const int warp = tid >> 5, lane = tid & 31;
    if (lane == 0) { red[0][warp] = s; red[1][warp] = ss; }
    __syncthreads();
    if (warp == 0) {
        float a0 = (lane < 8) ? red[0][lane] : 0.0f;
        float b0 = (lane < 8) ? red[1][lane] : 0.0f;
#pragma unroll
        for (int o = 4; o > 0; o >>= 1) {
            a0 += __shfl_down_sync(0xffffffffu, a0, o);
            b0 += __shfl_down_sync(0xffffffffu, b0, o);
        }
        if (lane == 0) { red[0][0] = a0; red[1][0] = b0; }
    }
    __syncthreads();
    const float mu   = red[0][0] * (1.0f / EE);
    const float var  = red[1][0] * (1.0f / EE) - mu * mu;
    const float rstd = rsqrtf(var + 1e-5f);

    float* po = out + (size_t)n * EE;
#pragma unroll
    for (int t = 0; t < 3; t++) {
        int e = tid + t * 256;
        float hv = (y[t] - mu) * rstd * scale[e] + bias[e];
        if (GATE) {
            int bidx = n >> 11;           // n / 2048
            float te = terrain[bidx * EE + e];
            hv *= 1.0f / (1.0f + __expf(-te));
        }
        po[e] = hv;
    }
}

// ---------------------------------------------------------------------------
// B-spline basis expansion: act (N x I) -> bases (N x I*8), contiguous [i*8+k]
// ---------------------------------------------------------------------------
__global__ void __launch_bounds__(256)
bases_kernel(const float* __restrict__ x, float* __restrict__ out, int total)
{
    int idx = blockIdx.x * blockDim.x + threadIdx.x;
    if (idx >= total) return;
    float b[8];
    bspline8(x[idx], b);
    float4 o0 = make_float4(b[0], b[1], b[2], b[3]);
    float4 o1 = make_float4(b[4], b[5], b[6], b[7]);
    *(float4*)(out + (size_t)idx * 8)     = o0;
    *(float4*)(out + (size_t)idx * 8 + 4) = o1;
}

// ---------------------------------------------------------------------------
// Launch
// ---------------------------------------------------------------------------
extern "C" void kernel_launch(void* const* d_in, const int* in_sizes, int n_in,
                              void* d_out, int out_size)
{
    const float* x       = (const float*)d_in[0];
    const float* terrain = (const float*)d_in[1];
    const float* qkv_w   = (const float*)d_in[2];
    const float* qkv_b   = (const float*)d_in[3];
    const float* out_w   = (const float*)d_in[4];
    const float* out_b   = (const float*)d_in[5];
    const float* ln1s    = (const float*)d_in[6];
    const float* ln1b    = (const float*)d_in[7];
    const float* bw0     = (const float*)d_in[8];
    const float* sw0     = (const float*)d_in[9];
    const float* bw1     = (const float*)d_in[10];
    const float* sw1     = (const float*)d_in[11];
    const float* ln2s    = (const float*)d_in[12];
    const float* ln2b    = (const float*)d_in[13];
    float* out = (float*)d_out;

    float *qkv, *ao, *proj, *h, *k0, *k1, *b0, *b1;
    cudaGetSymbolAddress((void**)&qkv,  g_qkv);
    cudaGetSymbolAddress((void**)&ao,   g_ao);
    cudaGetSymbolAddress((void**)&proj, g_proj);
    cudaGetSymbolAddress((void**)&h,    g_h);
    cudaGetSymbolAddress((void**)&k0,   g_k0);
    cudaGetSymbolAddress((void**)&k1,   g_k1);
    cudaGetSymbolAddress((void**)&b0,   g_b0);
    cudaGetSymbolAddress((void**)&b1,   g_b1);

    // 1. QKV projection: (4096 x 768) @ (2304 x 768)^T + bias
    gemm_nt<128,128,16,8,8,false,false,true>
        <<<dim3(F3/128, NN/128), 256>>>(x, qkv_w, qkv_b, qkv, NN, F3, EE);

    // 2. Attention
    attn_kernel<<<dim3(SS/64, BB*HH), 256>>>(qkv, ao);

    // 3. Output projection
    gemm_nt<128,64,16,8,4,false,false,true>
        <<<dim3(EE/64, NN/128), 256>>>(ao, out_w, out_b, proj, NN, EE, EE);

    // 4. h = LN(x + proj) * sigmoid(terrain)
    ln_kernel<true><<<NN, 256>>>(x, proj, ln1s, ln1b, terrain, h);

    // 5. bases0 = B-splines(h): (4096 x 6144)
    bases_kernel<<<(NN*EE + 255)/256, 256>>>(h, b0, NN*EE);

    // 6. kan0 = silu(h) @ base_w0^T
    gemm_nt<128,128,16,8,8,true,false,false>
        <<<dim3(DD1/128, NN/128), 256>>>(h, bw0, nullptr, k0, NN, DD1, EE);

    // 7. kan0 += bases0 @ spline_w0_flat^T   (K = 6144)
    gemm_nt<128,128,16,8,8,false,true,false>
        <<<dim3(DD1/128, NN/128), 256>>>(b0, sw0, nullptr, k0, NN, DD1, EE*KSP);

    // 8. bases1 = B-splines(kan0): (4096 x 12288)
    bases_kernel<<<(NN*DD1 + 255)/256, 256>>>(k0, b1, NN*DD1);

    // 9. kan1 = silu(kan0) @ base_w1^T
    gemm_nt<128,64,16,8,4,true,false,false>
        <<<dim3(EE/64, NN/128), 256>>>(k0, bw1, nullptr, k1, NN, EE, DD1);

    // 10. kan1 += bases1 @ spline_w1_flat^T  (K = 12288)
    gemm_nt<128,64,16,8,4,false,true,false>
        <<<dim3(EE/64, NN/128), 256>>>(b1, sw1, nullptr, k1, NN, EE, DD1*KSP);

    // 11. out = LN(h + kan1)
    ln_kernel<false><<<NN, 256>>>(h, k1, ln2s, ln2b, nullptr, out);
}

// round 14
// speedup vs baseline: 2.0365x; 2.0365x over previous
#include <cuda_runtime.h>
#include <math.h>
#include <cstdint>

// ---------------------------------------------------------------------------
// Problem constants
// ---------------------------------------------------------------------------
constexpr int BB   = 2;
constexpr int SS   = 2048;
constexpr int EE   = 768;
constexpr int HH   = 12;
constexpr int DH   = 64;
constexpr int NN   = BB * SS;        // 4096 rows
constexpr int F3   = 3 * EE;         // 2304
constexpr int DD1  = 1536;
constexpr int KA0  = 9 * EE;         // 6912
constexpr int KA1  = 9 * DD1;        // 13824

// ---------------------------------------------------------------------------
// Static scratch
// ---------------------------------------------------------------------------
__device__ float g_qkv [NN * F3];
__device__ float g_ao  [NN * EE];
__device__ float g_proj[NN * EE];
__device__ float g_h   [NN * EE];
__device__ float g_k0  [NN * DD1];
__device__ float g_k1  [NN * EE];
__device__ float g_a0  [NN * KA0];
__device__ float g_a1  [(size_t)NN * KA1];
__device__ float g_w0  [DD1 * KA0];
__device__ float g_w1  [EE * KA1];

// ---------------------------------------------------------------------------
// Helpers
// ---------------------------------------------------------------------------
__device__ __forceinline__ float siluf(float x) { return x / (1.0f + __expf(-x)); }
__device__ __forceinline__ float knot(int i)    { return (float)(i - 3) * 0.4f - 1.0f; }

__device__ __forceinline__ void bspline8(float v, float* __restrict__ b) {
    float t[11];
#pragma unroll
    for (int i = 0; i < 11; i++)
        t[i] = (v >= knot(i) && v < knot(i + 1)) ? 1.0f : 0.0f;
#pragma unroll
    for (int k = 1; k <= 3; k++) {
#pragma unroll
        for (int i = 0; i < 11; i++) {
            if (i < 11 - k) {
                float dl = knot(i + k)     - knot(i);
                float dr = knot(i + k + 1) - knot(i + 1);
                t[i] = (v - knot(i)) * (1.0f / dl) * t[i]
                     + (knot(i + k + 1) - v) * (1.0f / dr) * t[i + 1];
            }
        }
    }
#pragma unroll
    for (int i = 0; i < 8; i++) b[i] = t[i];
}

__device__ __forceinline__ uint32_t cvt_tf32(float f) {
    uint32_t u;
    asm("cvt.rna.tf32.f32 %0, %1;" : "=r"(u) : "f"(f));
    return u;
}

__device__ __forceinline__ void mma_tf32_16x8x8(float* c, const uint32_t* a,
                                                const uint32_t* b) {
    asm volatile(
        "mma.sync.aligned.m16n8k8.row.col.f32.tf32.tf32.f32 "
        "{%0,%1,%2,%3}, {%4,%5,%6,%7}, {%8,%9}, {%0,%1,%2,%3};"
        : "+f"(c[0]), "+f"(c[1]), "+f"(c[2]), "+f"(c[3])
        : "r"(a[0]), "r"(a[1]), "r"(a[2]), "r"(a[3]), "r"(b[0]), "r"(b[1]));
}

// ---------------------------------------------------------------------------
// TF32 mma.sync NT-GEMM:  C[n,m] = sum_k A[n,k]*B[m,k] (+ bias[m])
// A: N x K row-major, B: M x K row-major. Block 128x128, BK=32.
// 256 threads = 8 warps (2 x 4), warp tile 64 x 32.
// ---------------------------------------------------------------------------
template<bool BIAS>
__global__ void __launch_bounds__(256)
gemm_mma(const float* __restrict__ A, const float* __restrict__ B,
         const float* __restrict__ bias, float* __restrict__ C,
         int Kdim, int M)
{
    constexpr int SP = 36;                  // padded row stride (conflict-free)
    __shared__ uint32_t As[128 * SP];
    __shared__ uint32_t Bs[128 * SP];

    const int tid  = threadIdx.x;
    const int lane = tid & 31;
    const int warp = tid >> 5;
    const int wm   = warp >> 2;             // 0..1
    const int wn   = warp & 3;              // 0..3
    const int grp  = lane >> 2;             // 0..7
    const int qd   = lane & 3;              // 0..3

    const int row0 = blockIdx.y * 128;
    const int col0 = blockIdx.x * 128;
    const int NKB  = Kdim >> 5;

    const float* Abase = A + (size_t)row0 * Kdim;
    const float* Bbase = B + (size_t)col0 * Kdim;

    float acc[4][4][4];
#pragma unroll
    for (int i = 0; i < 4; i++)
#pragma unroll
        for (int j = 0; j < 4; j++)
#pragma unroll
            for (int t = 0; t < 4; t++) acc[i][j][t] = 0.0f;

    // staging registers: 4 float4 each for A and B (1024 float4 / 256 thr)
    float4 stA[4], stB[4];

    auto ldg_tile = [&](int kb) {
#pragma unroll
        for (int i = 0; i < 4; i++) {
            const int f  = tid + i * 256;       // 0..1023
            const int r  = f >> 3;
            const int c4 = f & 7;
            stA[i] = *(const float4*)(Abase + (size_t)r * Kdim + kb * 32 + c4 * 4);
            stB[i] = *(const float4*)(Bbase + (size_t)r * Kdim + kb * 32 + c4 * 4);
        }
    };
    auto sts_tile = [&]() {
#pragma unroll
        for (int i = 0; i < 4; i++) {
            const int f  = tid + i * 256;
            const int r  = f >> 3;
            const int c4 = f & 7;
            uint4 ta, tb;
            ta.x = cvt_tf32(stA[i].x); ta.y = cvt_tf32(stA[i].y);
            ta.z = cvt_tf32(stA[i].z); ta.w = cvt_tf32(stA[i].w);
            tb.x = cvt_tf32(stB[i].x); tb.y = cvt_tf32(stB[i].y);
            tb.z = cvt_tf32(stB[i].z); tb.w = cvt_tf32(stB[i].w);
            *(uint4*)&As[r * SP + c4 * 4] = ta;
            *(uint4*)&Bs[r * SP + c4 * 4] = tb;
        }
    };

    ldg_tile(0);

    for (int kb = 0; kb < NKB; kb++) {
        sts_tile();
        __syncthreads();
        if (kb + 1 < NKB) ldg_tile(kb + 1);

#pragma unroll
        for (int ks = 0; ks < 4; ks++) {
            const int kk = ks * 8;
            uint32_t af[4][4], bf[4][2];
#pragma unroll
            for (int mt = 0; mt < 4; mt++) {
                const int ar = wm * 64 + mt * 16 + grp;
                af[mt][0] = As[ar * SP + kk + qd];
                af[mt][1] = As[(ar + 8) * SP + kk + qd];
                af[mt][2] = As[ar * SP + kk + qd + 4];
                af[mt][3] = As[(ar + 8) * SP + kk + qd + 4];
            }
#pragma unroll
            for (int nt = 0; nt < 4; nt++) {
                const int br = wn * 32 + nt * 8 + grp;
                bf[nt][0] = Bs[br * SP + kk + qd];
                bf[nt][1] = Bs[br * SP + kk + qd + 4];
            }
#pragma unroll
            for (int mt = 0; mt < 4; mt++)
#pragma unroll
                for (int nt = 0; nt < 4; nt++)
                    mma_tf32_16x8x8(acc[mt][nt], af[mt], bf[nt]);
        }
        __syncthreads();
    }

    // epilogue
#pragma unroll
    for (int mt = 0; mt < 4; mt++) {
        const int r = row0 + wm * 64 + mt * 16 + grp;
#pragma unroll
        for (int nt = 0; nt < 4; nt++) {
            const int c = col0 + wn * 32 + nt * 8 + qd * 2;
            float2 v0 = make_float2(acc[mt][nt][0], acc[mt][nt][1]);
            float2 v1 = make_float2(acc[mt][nt][2], acc[mt][nt][3]);
            if (BIAS) {
                float2 bv = *(const float2*)(bias + c);
                v0.x += bv.x; v0.y += bv.y;
                v1.x += bv.x; v1.y += bv.y;
            }
            *(float2*)(C + (size_t)r * M + c)       = v0;
            *(float2*)(C + (size_t)(r + 8) * M + c) = v1;
        }
    }
}

// ---------------------------------------------------------------------------
// Flash attention, fp32 (R1-proven)
// ---------------------------------------------------------------------------
__global__ void __launch_bounds__(256)
attn_kernel(const float* __restrict__ qkv, float* __restrict__ ao)
{
    constexpr int BQ = 64, BKT = 32;
    __shared__ float Qt[BQ][DH + 1];
    __shared__ float Kt[BKT][DH + 1];
    __shared__ float Vt[BKT][DH + 1];
    __shared__ float Pt[BQ][BKT + 4];

    const int bh = blockIdx.y;
    const int b  = bh / HH;
    const int h  = bh % HH;
    const int q0 = blockIdx.x * BQ;
    const int tid  = threadIdx.x;
    const int quad = tid & 7;
    const int rg   = tid >> 3;

    {
        const float* qbase = qkv + ((size_t)(b * SS + q0)) * F3 + h * DH;
#pragma unroll
        for (int idx = tid; idx < BQ * (DH / 4); idx += 256) {
            int r  = idx >> 4;
            int c4 = idx & 15;
            float4 v = *(const float4*)(qbase + (size_t)r * F3 + c4 * 4);
            Qt[r][c4 * 4 + 0] = v.x; Qt[r][c4 * 4 + 1] = v.y;
            Qt[r][c4 * 4 + 2] = v.z; Qt[r][c4 * 4 + 3] = v.w;
        }
    }
    __syncthreads();

    float m[2] = {-1e30f, -1e30f};
    float l[2] = {0.0f, 0.0f};
    float acc_o[2][8];
#pragma unroll
    for (int jr = 0; jr < 2; jr++)
#pragma unroll
        for (int t = 0; t < 8; t++) acc_o[jr][t] = 0.0f;

    for (int kt = 0; kt < SS / BKT; kt++) {
        const float* kb = qkv + ((size_t)(b * SS + kt * BKT)) * F3 + EE + h * DH;
        const float* vb = kb + EE;
#pragma unroll
        for (int idx = tid; idx < BKT * (DH / 4); idx += 256) {
            int r  = idx >> 4;
            int c4 = idx & 15;
            float4 kv = *(const float4*)(kb + (size_t)r * F3 + c4 * 4);
            Kt[r][c4 * 4 + 0] = kv.x; Kt[r][c4 * 4 + 1] = kv.y;
            Kt[r][c4 * 4 + 2] = kv.z; Kt[r][c4 * 4 + 3] = kv.w;
            float4 vv = *(const float4*)(vb + (size_t)r * F3 + c4 * 4);
            Vt[r][c4 * 4 + 0] = vv.x; Vt[r][c4 * 4 + 1] = vv.y;
            Vt[r][c4 * 4 + 2] = vv.z; Vt[r][c4 * 4 + 3] = vv.w;
        }
        __syncthreads();

        float s[2][4] = {{0, 0, 0, 0}, {0, 0, 0, 0}};
#pragma unroll 4
        for (int d = 0; d < DH; d++) {
            float q0v = Qt[rg][d];
            float q1v = Qt[rg + 32][d];
#pragma unroll
            for (int jc = 0; jc < 4; jc++) {
                float kv = Kt[quad * 4 + jc][d];
                s[0][jc] = fmaf(q0v, kv, s[0][jc]);
                s[1][jc] = fmaf(q1v, kv, s[1][jc]);
            }
        }

#pragma unroll
        for (int jr = 0; jr < 2; jr++) {
            float sv[4];
            float mx = -1e30f;
#pragma unroll
            for (int jc = 0; jc < 4; jc++) {
                sv[jc] = s[jr][jc] * 0.125f;
                mx = fmaxf(mx, sv[jc]);
            }
#pragma unroll
            for (int o = 1; o < 8; o <<= 1)
                mx = fmaxf(mx, __shfl_xor_sync(0xffffffffu, mx, o));
            float newm = fmaxf(m[jr], mx);
            float lsum = 0.0f;
#pragma unroll
            for (int jc = 0; jc < 4; jc++) {
                float p = __expf(sv[jc] - newm);
                Pt[rg + jr * 32][quad * 4 + jc] = p;
                lsum += p;
            }
#pragma unroll
            for (int o = 1; o < 8; o <<= 1)
                lsum += __shfl_xor_sync(0xffffffffu, lsum, o);
            float corr = __expf(m[jr] - newm);
            l[jr] = l[jr] * corr + lsum;
            m[jr] = newm;
#pragma unroll
            for (int t = 0; t < 8; t++) acc_o[jr][t] *= corr;
        }
        __syncthreads();

#pragma unroll 4
        for (int c = 0; c < BKT; c++) {
            float p0 = Pt[rg][c];
            float p1 = Pt[rg + 32][c];
#pragma unroll
            for (int t = 0; t < 8; t++) {
                float vv = Vt[c][quad + 8 * t];
                acc_o[0][t] = fmaf(p0, vv, acc_o[0][t]);
                acc_o[1][t] = fmaf(p1, vv, acc_o[1][t]);
            }
        }
        __syncthreads();
    }

#pragma unroll
    for (int jr = 0; jr < 2; jr++) {
        float inv = 1.0f / l[jr];
        int srow = q0 + rg + jr * 32;
        float* op = ao + ((size_t)(b * SS + srow)) * EE + h * DH;
#pragma unroll
        for (int t = 0; t < 8; t++)
            op[quad + 8 * t] = acc_o[jr][t] * inv;
    }
}

// ---------------------------------------------------------------------------
// Fused residual + LayerNorm (+ optional sigmoid(terrain) gate)
// ---------------------------------------------------------------------------
template<bool GATE>
__global__ void __launch_bounds__(256)
ln_kernel(const float* __restrict__ a, const float* __restrict__ bsrc,
          const float* __restrict__ scale, const float* __restrict__ bias,
          const float* __restrict__ terrain, float* __restrict__ out)
{
    const int n = blockIdx.x;
    const int tid = threadIdx.x;
    const float* pa = a    + (size_t)n * EE;
    const float* pb = bsrc + (size_t)n * EE;

    float y[3];
    float s = 0.0f, ss = 0.0f;
#pragma unroll
    for (int t = 0; t < 3; t++) {
        int e = tid + t * 256;
        y[t] = pa[e] + pb[e];
        s  += y[t];
        ss += y[t] * y[t];
    }
#pragma unroll
    for (int o = 16; o > 0; o >>= 1) {
        s  += __shfl_down_sync(0xffffffffu, s,  o);
        ss += __shfl_down_sync(0xffffffffu, ss, o);
    }
    __shared__ float red[2][8];
    const int warp = tid >> 5, lane = tid & 31;
    if (lane == 0) { red[0][warp] = s; red[1][warp] = ss; }
    __syncthreads();
    if (warp == 0) {
        float a0 = (lane < 8) ? red[0][lane] : 0.0f;
        float b0 = (lane < 8) ? red[1][lane] : 0.0f;
#pragma unroll
        for (int o = 4; o > 0; o >>= 1) {
            a0 += __shfl_down_sync(0xffffffffu, a0, o);
            b0 += __shfl_down_sync(0xffffffffu, b0, o);
        }
        if (lane == 0) { red[0][0] = a0; red[1][0] = b0; }
    }
    __syncthreads();
    const float mu   = red[0][0] * (1.0f / EE);
    const float var  = red[1][0] * (1.0f / EE) - mu * mu;
    const float rstd = rsqrtf(var + 1e-5f);

    float* po = out + (size_t)n * EE;
#pragma unroll
    for (int t = 0; t < 3; t++) {
        int e = tid + t * 256;
        float hv = (y[t] - mu) * rstd * scale[e] + bias[e];
        if (GATE) {
            int bidx = n >> 11;
            float te = terrain[bidx * EE + e];
            hv *= 1.0f / (1.0f + __expf(-te));
        }
        po[e] = hv;
    }
}

// ---------------------------------------------------------------------------
// A' builder: x (N x I) -> out (N x 9I) = [bases | silu]
// ---------------------------------------------------------------------------
__global__ void __launch_bounds__(256)
bases_ext_kernel(const float* __restrict__ x, float* __restrict__ out,
                 int I, int total)
{
    int idx = blockIdx.x * blockDim.x + threadIdx.x;
    if (idx >= total) return;
    const int n = idx / I;
    const int i = idx - n * I;
    const float v = x[idx];
    float b[8];
    bspline8(v, b);
    float* po = out + (size_t)n * (9 * I);
    *(float4*)(po + i * 8)     = make_float4(b[0], b[1], b[2], b[3]);
    *(float4*)(po + i * 8 + 4) = make_float4(b[4], b[5], b[6], b[7]);
    po[8 * I + i] = siluf(v);
}

// ---------------------------------------------------------------------------
// Weight concat: out (O x 9I) = [spline_w (O x I x 8) flat | base_w (O x I)]
// ---------------------------------------------------------------------------
__global__ void __launch_bounds__(256)
wcat_kernel(const float* __restrict__ sw, const float* __restrict__ bw,
            float* __restrict__ out, int I, int total)
{
    int idx = blockIdx.x * blockDim.x + threadIdx.x;
    if (idx >= total) return;
    const int row = idx / (9 * I);
    const int c   = idx - row * (9 * I);
    float v;
    if (c < 8 * I) v = sw[(size_t)row * 8 * I + c];
    else           v = bw[(size_t)row * I + (c - 8 * I)];
    out[idx] = v;
}

// ---------------------------------------------------------------------------
// Launch
// ---------------------------------------------------------------------------
extern "C" void kernel_launch(void* const* d_in, const int* in_sizes, int n_in,
                              void* d_out, int out_size)
{
    const float* x       = (const float*)d_in[0];
    const float* terrain = (const float*)d_in[1];
    const float* qkv_w   = (const float*)d_in[2];
    const float* qkv_b   = (const float*)d_in[3];
    const float* out_w   = (const float*)d_in[4];
    const float* out_b   = (const float*)d_in[5];
    const float* ln1s    = (const float*)d_in[6];
    const float* ln1b    = (const float*)d_in[7];
    const float* bw0     = (const float*)d_in[8];
    const float* sw0     = (const float*)d_in[9];
    const float* bw1     = (const float*)d_in[10];
    const float* sw1     = (const float*)d_in[11];
    const float* ln2s    = (const float*)d_in[12];
    const float* ln2b    = (const float*)d_in[13];
    float* out = (float*)d_out;

    float *qkv, *ao, *proj, *h, *k0, *k1, *a0, *a1, *w0, *w1;
    cudaGetSymbolAddress((void**)&qkv, g_qkv);
    cudaGetSymbolAddress((void**)&ao,  g_ao);
    cudaGetSymbolAddress((void**)&proj,g_proj);
    cudaGetSymbolAddress((void**)&h,   g_h);
    cudaGetSymbolAddress((void**)&k0,  g_k0);
    cudaGetSymbolAddress((void**)&k1,  g_k1);
    cudaGetSymbolAddress((void**)&a0,  g_a0);
    cudaGetSymbolAddress((void**)&a1,  g_a1);
    cudaGetSymbolAddress((void**)&w0,  g_w0);
    cudaGetSymbolAddress((void**)&w1,  g_w1);

    // weight concats
    wcat_kernel<<<(DD1 * KA0 + 255) / 256, 256>>>(sw0, bw0, w0, EE,  DD1 * KA0);
    wcat_kernel<<<(EE  * KA1 + 255) / 256, 256>>>(sw1, bw1, w1, DD1, EE * KA1);

    // 1. QKV projection (tf32 mma.sync)
    gemm_mma<true><<<dim3(F3 / 128, NN / 128), 256>>>(x, qkv_w, qkv_b, qkv, EE, F3);

    // 2. Attention
    attn_kernel<<<dim3(SS / 64, BB * HH), 256>>>(qkv, ao);

    // 3. Output projection
    gemm_mma<true><<<dim3(EE / 128, NN / 128), 256>>>(ao, out_w, out_b, proj, EE, EE);

    // 4. h = LN(x + proj) * sigmoid(terrain)
    ln_kernel<true><<<NN, 256>>>(x, proj, ln1s, ln1b, terrain, h);

    // 5. A'0 = [bases(h) | silu(h)]
    bases_ext_kernel<<<(NN * EE + 255) / 256, 256>>>(h, a0, EE, NN * EE);

    // 6. kan0 = A'0 @ W'0^T  (K = 6912)
    gemm_mma<false><<<dim3(DD1 / 128, NN / 128), 256>>>(a0, w0, nullptr, k0, KA0, DD1);

    // 7. A'1 = [bases(kan0) | silu(kan0)]
    bases_ext_kernel<<<(NN * DD1 + 255) / 256, 256>>>(k0, a1, DD1, NN * DD1);

    // 8. kan1 = A'1 @ W'1^T  (K = 13824)
    gemm_mma<false><<<dim3(EE / 128, NN / 128), 256>>>(a1, w1, nullptr, k1, KA1, EE);

    // 9. out = LN(h + kan1)
    ln_kernel<false><<<NN, 256>>>(h, k1, ln2s, ln2b, nullptr, out);
}